// round 8
// baseline (speedup 1.0000x reference)
#include <cuda_runtime.h>

#define B 2
#define C 32
#define O 32
#define N 64
#define M 20
#define MM 400
#define MMM 8000
#define NN 4096

// Scratch (bss, allocation-free)
__device__ float g_Y2[(size_t)B * C * N * MM];   // fwd Y2 [bc][d][m]
__device__ float g_Y3[(size_t)B * C * MMM];      // [bc][kd][m]
__device__ float g_Zp[4][(size_t)B * O * MMM];   // 4 c-partial sums of Z
__device__ float g_cf [N * M];                   // fwd table  [d][kd]
__device__ float g_ciT[M * N];                   // inv table  [kd][d]

// ---------------------------------------------------------------------------
// Compile-time DCT coefficients (Taylor cos, folded to FFMA immediates)
// ---------------------------------------------------------------------------
__host__ __device__ constexpr double tcos(int a) {      // cos(pi*a/128)
    double x = 3.14159265358979323846264338327950288 * (double)a / 128.0;
    double x2 = x * x, term = 1.0, s = 1.0;
    for (int i = 1; i <= 16; i++) { term *= -x2 / (double)((2 * i - 1) * (2 * i)); s += term; }
    return s;
}
__host__ __device__ constexpr int redu(int k, int n) {
    int a = (k * (2 * n + 1)) % 256;
    return (a > 128) ? 256 - a : a;
}
__host__ __device__ constexpr float CF(int n, int k) {  // forward DCT-II coeff
    double c = tcos(redu(k, n));
    return (k == 0) ? 1.0f : (float)(2.0 * c);
}
__host__ __device__ constexpr float CI(int n, int k) {  // inverse DCT-III coeff
    double c = tcos(redu(k, n));
    return (float)(((k == 0) ? 1.0 : c) / 64.0);
}

template<int I> struct ic { static constexpr int value = I; };
template<int I, int Nn> struct SF {
    template<class F> __device__ __forceinline__ static void run(F&& f) {
        f(ic<I>{}); SF<I + 1, Nn>::run(f);
    }
};
template<int Nn> struct SF<Nn, Nn> {
    template<class F> __device__ __forceinline__ static void run(F&&) {}
};
template<int Nn, class F> __device__ __forceinline__ void static_for(F&& f) { SF<0, Nn>::run(f); }

// cp.async helpers
__device__ __forceinline__ unsigned smem_u32(const void* p) {
    return (unsigned)__cvta_generic_to_shared(p);
}
__device__ __forceinline__ void cp_async16(unsigned dst, const void* src, int szbytes) {
    asm volatile("cp.async.cg.shared.global [%0], [%1], 16, %2;\n"
                 :: "r"(dst), "l"(src), "r"(szbytes));
}
__device__ __forceinline__ void cp_async_wait_all() {
    asm volatile("cp.async.commit_group;\n");
    asm volatile("cp.async.wait_group 0;\n");
}

// ---------------------------------------------------------------------------
__global__ void init_mats_k() {
    int t = blockIdx.x * blockDim.x + threadIdx.x;
    if (t < N * M) {
        int n = t / M, k = t % M;
        g_cf[t] = CF(n, k);
        int k2 = t / N, n2 = t % N;
        g_ciT[t] = CI(n2, k2);
    }
}

// ---------------------------------------------------------------------------
// fwd_wh: x[slice][h][w] -> Y2[slice][kh][kw], 1 slice per 128-thread block.
// Butterfly: CF(63-n,k) = (-1)^k CF(n,k).
// ---------------------------------------------------------------------------
template<int KW0>
__device__ __forceinline__ void fwd_s1(const float* __restrict__ xr, float* __restrict__ tp) {
    float acc[10];
#pragma unroll
    for (int k = 0; k < 10; k++) acc[k] = 0.f;
    static_for<8>([&](auto W4) {
        constexpr int w4 = W4.value;
        float4 av = *(const float4*)(xr + w4 * 4);
        float4 bv = *(const float4*)(xr + 60 - w4 * 4);
        float s0 = av.x + bv.w, d0 = av.x - bv.w;
        float s1 = av.y + bv.z, d1 = av.y - bv.z;
        float s2 = av.z + bv.y, d2 = av.z - bv.y;
        float s3 = av.w + bv.x, d3 = av.w - bv.x;
        static_for<10>([&](auto K) {
            constexpr int k = K.value;
            constexpr int kw = KW0 + k;
            constexpr float c0 = CF(w4 * 4 + 0, kw);
            constexpr float c1 = CF(w4 * 4 + 1, kw);
            constexpr float c2 = CF(w4 * 4 + 2, kw);
            constexpr float c3 = CF(w4 * 4 + 3, kw);
            if constexpr (kw & 1) {
                acc[k] += d0 * c0; acc[k] += d1 * c1;
                acc[k] += d2 * c2; acc[k] += d3 * c3;
            } else {
                acc[k] += s0 * c0; acc[k] += s1 * c1;
                acc[k] += s2 * c2; acc[k] += s3 * c3;
            }
        });
    });
#pragma unroll
    for (int k = 0; k < 10; k++) tp[KW0 + k] = acc[k];
}

template<int KH0>
__device__ __forceinline__ void fwd_s2(const float* __restrict__ tcol, float* __restrict__ outp, bool act) {
    float acc[5] = {0.f, 0.f, 0.f, 0.f, 0.f};
    static_for<32>([&](auto H) {
        constexpr int h = H.value;
        float a = tcol[h * 21], b = tcol[(63 - h) * 21];
        float s = a + b, d = a - b;
        static_for<5>([&](auto K) {
            constexpr int k = K.value;
            constexpr int kh = KH0 + k;
            constexpr float c = CF(h, kh);
            acc[k] += ((kh & 1) ? d : s) * c;
        });
    });
    if (act) {
#pragma unroll
        for (int k = 0; k < 5; k++) outp[(KH0 + k) * 20] = acc[k];
    }
}

__global__ __launch_bounds__(128) void fwd_wh_k(const float* __restrict__ x) {
    __shared__ float xs[64 * 68];
    __shared__ float tmp[64 * 21];
    int t = threadIdx.x, wid = t >> 5, lane = t & 31;
    int slice = blockIdx.x;
    const float* xp = x + (size_t)slice * NN;
#pragma unroll
    for (int r = 0; r < 8; r++) {
        int idx = t + r * 128;
        int h = idx >> 4, w4 = idx & 15;
        cp_async16(smem_u32(&xs[h * 68 + w4 * 4]), xp + idx * 4, 16);
    }
    cp_async_wait_all();
    __syncthreads();
    {   // stage 1
        int h = (wid >> 1) * 32 + lane;
        const float* xr = &xs[h * 68];
        float* tp = &tmp[h * 21];
        if (wid & 1) fwd_s1<10>(xr, tp); else fwd_s1<0>(xr, tp);
    }
    __syncthreads();
    {   // stage 2
        bool act = lane < 20;
        int kwc = act ? lane : 0;
        const float* tcol = &tmp[kwc];
        float* outp = g_Y2 + (size_t)slice * MM + kwc;
        switch (wid) {
            case 0: fwd_s2<0>(tcol, outp, act); break;
            case 1: fwd_s2<5>(tcol, outp, act); break;
            case 2: fwd_s2<10>(tcol, outp, act); break;
            default: fwd_s2<15>(tcol, outp, act); break;
        }
    }
}

// ---------------------------------------------------------------------------
// fwd_d: Y2[bc][d][m] -> Y3[bc][kd][m]   grid (64 bc, 4 mtile), block 128
// ---------------------------------------------------------------------------
__global__ __launch_bounds__(128) void fwd_d_k() {
    __shared__ float ys2[64 * 100];
    __shared__ float cfs[N * M];
    int bc = blockIdx.x, mt = blockIdx.y;
    int t = threadIdx.x, wid = t >> 5, lane = t & 31;
    const float* src = g_Y2 + (size_t)bc * (N * MM) + mt * 100;
    for (int i = t; i < 1600; i += 128) {
        int d = i / 25, j = (i % 25) * 4;
        *(float4*)&ys2[d * 100 + j] = *(const float4*)(src + (size_t)d * MM + j);
    }
    for (int i = t; i < N * M; i += 128) cfs[i] = g_cf[i];
    __syncthreads();
    int KD0 = wid * 5;
    bool act = lane < 25;
    int ml = act ? lane * 4 : 0;
    float4 acc[5];
#pragma unroll
    for (int k = 0; k < 5; k++) acc[k] = make_float4(0.f, 0.f, 0.f, 0.f);
#pragma unroll 4
    for (int d = 0; d < 64; d++) {
        float4 v = *(const float4*)&ys2[d * 100 + ml];
#pragma unroll
        for (int k = 0; k < 5; k++) {
            float cc = cfs[d * 20 + KD0 + k];
            acc[k].x += cc * v.x; acc[k].y += cc * v.y;
            acc[k].z += cc * v.z; acc[k].w += cc * v.w;
        }
    }
    if (act) {
        float* q = g_Y3 + (size_t)bc * MMM + mt * 100 + lane * 4;
#pragma unroll
        for (int k = 0; k < 5; k++) *(float4*)(q + (size_t)(KD0 + k) * MM) = acc[k];
    }
}

// ---------------------------------------------------------------------------
// mix: partial Z over 8 channels per block, cp.async staged.
// grid (63 m-tiles of 128, 8 o-tiles of 4, 4 c-quarters), block 128.
// ---------------------------------------------------------------------------
__global__ __launch_bounds__(128) void mix_k(const float* __restrict__ w) {
    __shared__ float ys[2 * 8 * 128];     // 8 KB
    __shared__ float ws[8 * 4 * 128];     // 16 KB
    int mbase = blockIdx.x * 128;
    int o0 = blockIdx.y * 4;
    int c0 = blockIdx.z * 8;
    int t = threadIdx.x, wid = t >> 5, lane = t & 31;
#pragma unroll
    for (int r = 0; r < 4; r++) {         // ys: 512 float4
        int i = t + r * 128;
        int b = i >> 8, c = (i >> 5) & 7, m4 = i & 31;
        int m = mbase + m4 * 4;
        const float* src = g_Y3 + (size_t)(b * C + c0 + c) * MMM + ((m < MMM) ? m : 0);
        cp_async16(smem_u32(&ys[(b * 8 + c) * 128 + m4 * 4]), src, (m < MMM) ? 16 : 0);
    }
#pragma unroll
    for (int r = 0; r < 8; r++) {         // ws: 1024 float4
        int i = t + r * 128;
        int c = i >> 7, ol = (i >> 5) & 3, m4 = i & 31;
        int m = mbase + m4 * 4;
        const float* src = w + ((size_t)(c0 + c) * O + o0 + ol) * MMM + ((m < MMM) ? m : 0);
        cp_async16(smem_u32(&ws[(c * 4 + ol) * 128 + m4 * 4]), src, (m < MMM) ? 16 : 0);
    }
    cp_async_wait_all();
    __syncthreads();
    int o = o0 + wid;
    int m0 = mbase + lane * 4;
    float4 a0 = make_float4(0.f,0.f,0.f,0.f), a1 = a0;
#pragma unroll
    for (int c = 0; c < 8; c++) {
        float4 wv = *(const float4*)&ws[(c * 4 + wid) * 128 + lane * 4];
        float4 y0 = *(const float4*)&ys[c * 128 + lane * 4];
        float4 y1 = *(const float4*)&ys[(8 + c) * 128 + lane * 4];
        a0.x += y0.x*wv.x; a0.y += y0.y*wv.y; a0.z += y0.z*wv.z; a0.w += y0.w*wv.w;
        a1.x += y1.x*wv.x; a1.y += y1.y*wv.y; a1.z += y1.z*wv.z; a1.w += y1.w*wv.w;
    }
    if (m0 < MMM) {
        float* Zp = g_Zp[blockIdx.z];
        *(float4*)(Zp + (size_t)o * MMM + m0) = a0;
        *(float4*)(Zp + (size_t)(O + o) * MMM + m0) = a1;
    }
}

// ---------------------------------------------------------------------------
// inv_dhw: sum(Zp)[bo][kd][m] -> out[bo][d][h][w], fused d-expand + h/w butterfly.
// grid (64 bo, 4 d-quarters), block 256.
// ---------------------------------------------------------------------------
template<int HB>
__device__ __forceinline__ void inv_s1(const float* __restrict__ zcol, float* __restrict__ tcol, bool act) {
    float E[8], Od[8];
#pragma unroll
    for (int i = 0; i < 8; i++) { E[i] = 0.f; Od[i] = 0.f; }
    static_for<20>([&](auto KH) {
        constexpr int kh = KH.value;
        float zv = zcol[kh * 20];
        static_for<8>([&](auto I) {
            constexpr int i = I.value;
            constexpr float c = CI(HB + i, kh);
            if constexpr (kh & 1) Od[i] += zv * c; else E[i] += zv * c;
        });
    });
    if (act) {
#pragma unroll
        for (int i = 0; i < 8; i++) {
            tcol[(HB + i) * 21] = E[i] + Od[i];
            tcol[(63 - HB - i) * 21] = E[i] - Od[i];
        }
    }
}

template<int W0>
__device__ __forceinline__ void inv_s2(const float* __restrict__ trow, float* __restrict__ orow) {
    float E[16], Od[16];
#pragma unroll
    for (int i = 0; i < 16; i++) { E[i] = 0.f; Od[i] = 0.f; }
    static_for<20>([&](auto KW) {
        constexpr int kw = KW.value;
        float tv = trow[kw];
        static_for<16>([&](auto I) {
            constexpr int i = I.value;
            constexpr float c = CI(W0 + i, kw);
            if constexpr (kw & 1) Od[i] += tv * c; else E[i] += tv * c;
        });
    });
#pragma unroll
    for (int j = 0; j < 4; j++) {
        float4 v = make_float4(E[j*4+0] + Od[j*4+0], E[j*4+1] + Od[j*4+1],
                               E[j*4+2] + Od[j*4+2], E[j*4+3] + Od[j*4+3]);
        *(float4*)(orow + W0 + j * 4) = v;
    }
#pragma unroll
    for (int j = 0; j < 4; j++) {
        float4 v = make_float4(E[15-(j*4+0)] - Od[15-(j*4+0)], E[15-(j*4+1)] - Od[15-(j*4+1)],
                               E[15-(j*4+2)] - Od[15-(j*4+2)], E[15-(j*4+3)] - Od[15-(j*4+3)]);
        *(float4*)(orow + (48 - W0) + j * 4) = v;
    }
}

__global__ __launch_bounds__(256) void inv_dhw_k(float* __restrict__ out) {
    __shared__ float zs[MMM];          // 32 KB; reused as u1s[16][400] after phase A
    __shared__ float tmp[2][64 * 21];  // 10.75 KB
    __shared__ float cis[M * 16];      // [kd][dl] for this block's 16 d
    int bo = blockIdx.x, d0 = blockIdx.y * 16;
    int t = threadIdx.x, wid = t >> 5, lane = t & 31;
    for (int i = t; i < 2000; i += 256) {
        float4 a = *(const float4*)(g_Zp[0] + (size_t)bo * MMM + i * 4);
        float4 b = *(const float4*)(g_Zp[1] + (size_t)bo * MMM + i * 4);
        float4 c = *(const float4*)(g_Zp[2] + (size_t)bo * MMM + i * 4);
        float4 d = *(const float4*)(g_Zp[3] + (size_t)bo * MMM + i * 4);
        a.x += b.x + c.x + d.x; a.y += b.y + c.y + d.y;
        a.z += b.z + c.z + d.z; a.w += b.w + c.w + d.w;
        *(float4*)&zs[i * 4] = a;
    }
    for (int i = t; i < 320; i += 256) {        // FIX: strided (was if(t<320) with 256 threads)
        int kd = i / 16, dl = i % 16;
        cis[i] = g_ciT[kd * 64 + d0 + dl];
    }
    __syncthreads();
    // phase A: d-expansion, warp -> 2 local d, registers hold [4 mt][2 d] float4
    bool act = lane < 25;
    int ml = act ? lane * 4 : 0;
    int dl0 = wid * 2;
    float4 acc[4][2];
#pragma unroll
    for (int mt = 0; mt < 4; mt++) { acc[mt][0] = make_float4(0.f,0.f,0.f,0.f); acc[mt][1] = acc[mt][0]; }
#pragma unroll
    for (int kd = 0; kd < M; kd++) {
        float c0 = cis[kd * 16 + dl0], c1 = cis[kd * 16 + dl0 + 1];
#pragma unroll
        for (int mt = 0; mt < 4; mt++) {
            float4 v = *(const float4*)&zs[kd * MM + mt * 100 + ml];
            acc[mt][0].x += c0 * v.x; acc[mt][0].y += c0 * v.y;
            acc[mt][0].z += c0 * v.z; acc[mt][0].w += c0 * v.w;
            acc[mt][1].x += c1 * v.x; acc[mt][1].y += c1 * v.y;
            acc[mt][1].z += c1 * v.z; acc[mt][1].w += c1 * v.w;
        }
    }
    __syncthreads();      // all zs reads done
    if (act) {
#pragma unroll
        for (int mt = 0; mt < 4; mt++) {
            *(float4*)&zs[dl0 * MM + mt * 100 + ml] = acc[mt][0];
            *(float4*)&zs[(dl0 + 1) * MM + mt * 100 + ml] = acc[mt][1];
        }
    }
    __syncthreads();
    // phase B: 8 rounds x 2 slices; warps 0-3 -> slice 2r, warps 4-7 -> 2r+1
    int half = wid >> 2, ws4 = wid & 3;
    for (int r = 0; r < 8; r++) {
        int dl = r * 2 + half;
        {
            bool a2 = lane < 20;
            int kwc = a2 ? lane : 0;
            const float* zcol = &zs[dl * MM + kwc];
            float* tcol = &tmp[half][kwc];
            switch (ws4) {
                case 0: inv_s1<0>(zcol, tcol, a2); break;
                case 1: inv_s1<8>(zcol, tcol, a2); break;
                case 2: inv_s1<16>(zcol, tcol, a2); break;
                default: inv_s1<24>(zcol, tcol, a2); break;
            }
        }
        __syncthreads();
        {
            int h = (ws4 & 1) * 32 + lane;
            const float* trow = &tmp[half][h * 21];
            float* orow = out + ((size_t)bo * 64 + d0 + dl) * NN + h * 64;
            if (ws4 >> 1) inv_s2<16>(trow, orow); else inv_s2<0>(trow, orow);
        }
        __syncthreads();
    }
}

// ---------------------------------------------------------------------------
extern "C" void kernel_launch(void* const* d_in, const int* in_sizes, int n_in,
                              void* d_out, int out_size) {
    const float* x = (const float*)d_in[0];       // (2,32,64,64,64)
    const float* w = (const float*)d_in[1];       // (32,32,20,20,20)
    float* out = (float*)d_out;                   // (2,32,64,64,64)

    init_mats_k<<<5, 256>>>();
    fwd_wh_k<<<B * C * N, 128>>>(x);              // 4096 blocks
    {
        dim3 g(B * C, 4);
        fwd_d_k<<<g, 128>>>();                    // 256 blocks
    }
    {
        dim3 g(63, 8, 4);
        mix_k<<<g, 128>>>(w);                     // 2016 blocks
    }
    {
        dim3 g(B * O, 4);
        inv_dhw_k<<<g, 256>>>(out);               // 256 blocks
    }
}

// round 9
// speedup vs baseline: 1.6164x; 1.6164x over previous
#include <cuda_runtime.h>
#include <math.h>

#define B 2
#define C 32
#define O 32
#define N 64
#define M 20
#define MM 400
#define MMM 8000
#define NN 4096

// Scratch (bss, allocation-free)
__device__ float g_Y2[(size_t)B * C * N * MM];   // fwd Y2 [bc][d][m]; reused as U1 [bo][d][m]
__device__ float g_Y3[(size_t)B * C * MMM];      // [bc][kd][m]
__device__ float g_Zp[4][(size_t)B * O * MMM];   // 4 c-partial sums of Z

#define PI_F 3.14159265358979323846f

// ---------------------------------------------------------------------------
// Compile-time DCT coefficients (Taylor cos, folded to FFMA immediates)
// ---------------------------------------------------------------------------
__host__ __device__ constexpr double tcos(int a) {      // cos(pi*a/128)
    double x = 3.14159265358979323846264338327950288 * (double)a / 128.0;
    double x2 = x * x, term = 1.0, s = 1.0;
    for (int i = 1; i <= 16; i++) { term *= -x2 / (double)((2 * i - 1) * (2 * i)); s += term; }
    return s;
}
__host__ __device__ constexpr int redu(int k, int n) {
    int a = (k * (2 * n + 1)) % 256;
    return (a > 128) ? 256 - a : a;
}
__host__ __device__ constexpr float CF(int n, int k) {  // forward DCT-II coeff
    double c = tcos(redu(k, n));
    return (k == 0) ? 1.0f : (float)(2.0 * c);
}
__host__ __device__ constexpr float CI(int n, int k) {  // inverse DCT-III coeff
    double c = tcos(redu(k, n));
    return (float)(((k == 0) ? 1.0 : c) / 64.0);
}

template<int I> struct ic { static constexpr int value = I; };
template<int I, int Nn> struct SF {
    template<class F> __device__ __forceinline__ static void run(F&& f) {
        f(ic<I>{}); SF<I + 1, Nn>::run(f);
    }
};
template<int Nn> struct SF<Nn, Nn> {
    template<class F> __device__ __forceinline__ static void run(F&&) {}
};
template<int Nn, class F> __device__ __forceinline__ void static_for(F&& f) { SF<0, Nn>::run(f); }

// cp.async helpers
__device__ __forceinline__ unsigned smem_u32(const void* p) {
    return (unsigned)__cvta_generic_to_shared(p);
}
__device__ __forceinline__ void cp_async16(unsigned dst, const void* src, int szbytes) {
    asm volatile("cp.async.cg.shared.global [%0], [%1], 16, %2;\n"
                 :: "r"(dst), "l"(src), "r"(szbytes));
}
__device__ __forceinline__ void cp_async_wait_all() {
    asm volatile("cp.async.commit_group;\n");
    asm volatile("cp.async.wait_group 0;\n");
}

// ---------------------------------------------------------------------------
// fwd_wh: x[slice][h][w] -> Y2[slice][kh][kw], 1 slice per 128-thread block.
// Butterfly: CF(63-n,k) = (-1)^k CF(n,k).
// Stage 1 writes tmp TRANSPOSED [kw][h] (stride 68) so stage 2 reads rows
// with LDS.128 (conflict-free: 68 % 32 = 4).
// ---------------------------------------------------------------------------
template<int KW0>
__device__ __forceinline__ void fwd_s1(const float* __restrict__ xr, float* __restrict__ tT, int h) {
    float acc[10];
#pragma unroll
    for (int k = 0; k < 10; k++) acc[k] = 0.f;
    static_for<8>([&](auto W4) {
        constexpr int w4 = W4.value;
        float4 av = *(const float4*)(xr + w4 * 4);
        float4 bv = *(const float4*)(xr + 60 - w4 * 4);
        float s0 = av.x + bv.w, d0 = av.x - bv.w;
        float s1 = av.y + bv.z, d1 = av.y - bv.z;
        float s2 = av.z + bv.y, d2 = av.z - bv.y;
        float s3 = av.w + bv.x, d3 = av.w - bv.x;
        static_for<10>([&](auto K) {
            constexpr int k = K.value;
            constexpr int kw = KW0 + k;
            constexpr float c0 = CF(w4 * 4 + 0, kw);
            constexpr float c1 = CF(w4 * 4 + 1, kw);
            constexpr float c2 = CF(w4 * 4 + 2, kw);
            constexpr float c3 = CF(w4 * 4 + 3, kw);
            if constexpr (kw & 1) {
                acc[k] += d0 * c0; acc[k] += d1 * c1;
                acc[k] += d2 * c2; acc[k] += d3 * c3;
            } else {
                acc[k] += s0 * c0; acc[k] += s1 * c1;
                acc[k] += s2 * c2; acc[k] += s3 * c3;
            }
        });
    });
#pragma unroll
    for (int k = 0; k < 10; k++) tT[(KW0 + k) * 68 + h] = acc[k];
}

template<int KH0>
__device__ __forceinline__ void fwd_s2(const float* __restrict__ trow, float* __restrict__ outp, bool act) {
    float acc[5] = {0.f, 0.f, 0.f, 0.f, 0.f};
    static_for<8>([&](auto H4) {
        constexpr int h4 = H4.value;
        float4 av = *(const float4*)(trow + h4 * 4);
        float4 bv = *(const float4*)(trow + 60 - h4 * 4);
        float s0 = av.x + bv.w, d0 = av.x - bv.w;
        float s1 = av.y + bv.z, d1 = av.y - bv.z;
        float s2 = av.z + bv.y, d2 = av.z - bv.y;
        float s3 = av.w + bv.x, d3 = av.w - bv.x;
        static_for<5>([&](auto K) {
            constexpr int k = K.value;
            constexpr int kh = KH0 + k;
            constexpr float c0 = CF(h4 * 4 + 0, kh);
            constexpr float c1 = CF(h4 * 4 + 1, kh);
            constexpr float c2 = CF(h4 * 4 + 2, kh);
            constexpr float c3 = CF(h4 * 4 + 3, kh);
            if constexpr (kh & 1) {
                acc[k] += d0 * c0; acc[k] += d1 * c1;
                acc[k] += d2 * c2; acc[k] += d3 * c3;
            } else {
                acc[k] += s0 * c0; acc[k] += s1 * c1;
                acc[k] += s2 * c2; acc[k] += s3 * c3;
            }
        });
    });
    if (act) {
#pragma unroll
        for (int k = 0; k < 5; k++) outp[(KH0 + k) * 20] = acc[k];
    }
}

__global__ __launch_bounds__(128) void fwd_wh_k(const float* __restrict__ x) {
    __shared__ float xs[64 * 68];         // [h][w], stride 68
    __shared__ float tT[20 * 68];         // [kw][h], stride 68
    int t = threadIdx.x, wid = t >> 5, lane = t & 31;
    int slice = blockIdx.x;
    const float* xp = x + (size_t)slice * NN;
#pragma unroll
    for (int r = 0; r < 8; r++) {
        int idx = t + r * 128;            // float4 index 0..1023
        int h = idx >> 4, w4 = idx & 15;
        *(float4*)&xs[h * 68 + w4 * 4] = *(const float4*)(xp + idx * 4);
    }
    __syncthreads();
    {   // stage 1: tT[kw][h] = sum_w xs[h][w]*CF(w,kw)   (butterfly)
        int h = (wid >> 1) * 32 + lane;
        const float* xr = &xs[h * 68];
        if (wid & 1) fwd_s1<10>(xr, tT, h); else fwd_s1<0>(xr, tT, h);
    }
    __syncthreads();
    {   // stage 2: Y2[kh][kw] = sum_h CF(h,kh)*tT[kw][h]  (butterfly, LDS.128)
        bool act = lane < 20;
        int kwc = act ? lane : 0;
        const float* trow = &tT[kwc * 68];
        float* outp = g_Y2 + (size_t)slice * MM + kwc;
        switch (wid) {
            case 0: fwd_s2<0>(trow, outp, act); break;
            case 1: fwd_s2<5>(trow, outp, act); break;
            case 2: fwd_s2<10>(trow, outp, act); break;
            default: fwd_s2<15>(trow, outp, act); break;
        }
    }
}

// ---------------------------------------------------------------------------
// fwd_d: Y2[bc][d][m] -> Y3[bc][kd][m]   grid (64 bc, 4 mtile), block 128.
// Coefficient table computed in-kernel via cosf (no init kernel).
// ---------------------------------------------------------------------------
__global__ __launch_bounds__(128) void fwd_d_k() {
    __shared__ float ys2[64 * 100];
    __shared__ float cfs[N * M];          // [d][kd]
    int bc = blockIdx.x, mt = blockIdx.y;
    int t = threadIdx.x, wid = t >> 5, lane = t & 31;
    const float* src = g_Y2 + (size_t)bc * (N * MM) + mt * 100;
    for (int i = t; i < 1600; i += 128) {
        int d = i / 25, j = (i % 25) * 4;
        *(float4*)&ys2[d * 100 + j] = *(const float4*)(src + (size_t)d * MM + j);
    }
    for (int i = t; i < N * M; i += 128) {
        int d = i / 20, k = i % 20;
        cfs[i] = (k == 0) ? 1.0f : 2.0f * cosf(PI_F * (float)(k * (2 * d + 1)) / 128.0f);
    }
    __syncthreads();
    int KD0 = wid * 5;
    bool act = lane < 25;
    int ml = act ? lane * 4 : 0;
    float4 acc[5];
#pragma unroll
    for (int k = 0; k < 5; k++) acc[k] = make_float4(0.f, 0.f, 0.f, 0.f);
#pragma unroll 4
    for (int d = 0; d < 64; d++) {
        float4 v = *(const float4*)&ys2[d * 100 + ml];
#pragma unroll
        for (int k = 0; k < 5; k++) {
            float cc = cfs[d * 20 + KD0 + k];
            acc[k].x += cc * v.x; acc[k].y += cc * v.y;
            acc[k].z += cc * v.z; acc[k].w += cc * v.w;
        }
    }
    if (act) {
        float* q = g_Y3 + (size_t)bc * MMM + mt * 100 + lane * 4;
#pragma unroll
        for (int k = 0; k < 5; k++) *(float4*)(q + (size_t)(KD0 + k) * MM) = acc[k];
    }
}

// ---------------------------------------------------------------------------
// mix: partial Z over 8 channels per block, cp.async staged.
// grid (63 m-tiles of 128, 8 o-tiles of 4, 4 c-quarters), block 128.
// ---------------------------------------------------------------------------
__global__ __launch_bounds__(128) void mix_k(const float* __restrict__ w) {
    __shared__ float ys[2 * 8 * 128];     // 8 KB
    __shared__ float ws[8 * 4 * 128];     // 16 KB
    int mbase = blockIdx.x * 128;
    int o0 = blockIdx.y * 4;
    int c0 = blockIdx.z * 8;
    int t = threadIdx.x, wid = t >> 5, lane = t & 31;
#pragma unroll
    for (int r = 0; r < 4; r++) {         // ys: 512 float4
        int i = t + r * 128;
        int b = i >> 8, c = (i >> 5) & 7, m4 = i & 31;
        int m = mbase + m4 * 4;
        const float* src = g_Y3 + (size_t)(b * C + c0 + c) * MMM + ((m < MMM) ? m : 0);
        cp_async16(smem_u32(&ys[(b * 8 + c) * 128 + m4 * 4]), src, (m < MMM) ? 16 : 0);
    }
#pragma unroll
    for (int r = 0; r < 8; r++) {         // ws: 1024 float4
        int i = t + r * 128;
        int c = i >> 7, ol = (i >> 5) & 3, m4 = i & 31;
        int m = mbase + m4 * 4;
        const float* src = w + ((size_t)(c0 + c) * O + o0 + ol) * MMM + ((m < MMM) ? m : 0);
        cp_async16(smem_u32(&ws[(c * 4 + ol) * 128 + m4 * 4]), src, (m < MMM) ? 16 : 0);
    }
    cp_async_wait_all();
    __syncthreads();
    int o = o0 + wid;
    int m0 = mbase + lane * 4;
    float4 a0 = make_float4(0.f,0.f,0.f,0.f), a1 = a0;
#pragma unroll
    for (int c = 0; c < 8; c++) {
        float4 wv = *(const float4*)&ws[(c * 4 + wid) * 128 + lane * 4];
        float4 y0 = *(const float4*)&ys[c * 128 + lane * 4];
        float4 y1 = *(const float4*)&ys[(8 + c) * 128 + lane * 4];
        a0.x += y0.x*wv.x; a0.y += y0.y*wv.y; a0.z += y0.z*wv.z; a0.w += y0.w*wv.w;
        a1.x += y1.x*wv.x; a1.y += y1.y*wv.y; a1.z += y1.z*wv.z; a1.w += y1.w*wv.w;
    }
    if (m0 < MMM) {
        float* Zp = g_Zp[blockIdx.z];
        *(float4*)(Zp + (size_t)o * MMM + m0) = a0;
        *(float4*)(Zp + (size_t)(O + o) * MMM + m0) = a1;
    }
}

// ---------------------------------------------------------------------------
// inv_d: sum(Zp)[bo][kd][m] -> U1[bo][d][m] (into g_Y2)  grid (64 bo, 4 dquarter)
// Coefficient table computed in-kernel via cosf.
// ---------------------------------------------------------------------------
__global__ __launch_bounds__(256) void inv_d_k() {
    __shared__ float zs[MMM];
    __shared__ float cis[M * N];      // [kd][d]
    int bo = blockIdx.x;
    int t = threadIdx.x, wid = t >> 5, lane = t & 31;
    const float* p0 = g_Zp[0] + (size_t)bo * MMM;
    const float* p1 = g_Zp[1] + (size_t)bo * MMM;
    const float* p2 = g_Zp[2] + (size_t)bo * MMM;
    const float* p3 = g_Zp[3] + (size_t)bo * MMM;
    for (int i = t; i < MMM / 4; i += 256) {
        float4 a = *(const float4*)(p0 + i * 4);
        float4 b = *(const float4*)(p1 + i * 4);
        float4 c = *(const float4*)(p2 + i * 4);
        float4 d = *(const float4*)(p3 + i * 4);
        a.x += b.x + c.x + d.x; a.y += b.y + c.y + d.y;
        a.z += b.z + c.z + d.z; a.w += b.w + c.w + d.w;
        *(float4*)&zs[i * 4] = a;
    }
    for (int i = t; i < M * N; i += 256) {
        int kd = i / 64, d = i % 64;
        float v = (kd == 0) ? 1.0f : cosf(PI_F * (float)(kd * (2 * d + 1)) / 128.0f);
        cis[i] = v * (1.0f / 64.0f);
    }
    __syncthreads();
    int mt = wid & 3;
    int d0 = blockIdx.y * 16 + (wid >> 2) * 8;
    bool act = lane < 25;
    int ml = act ? lane * 4 : 0;
    int m0 = mt * 100 + ml;
    float4 acc[8];
#pragma unroll
    for (int i = 0; i < 8; i++) acc[i] = make_float4(0.f,0.f,0.f,0.f);
#pragma unroll
    for (int kd = 0; kd < M; kd++) {
        float4 v = *(const float4*)&zs[kd * MM + m0];
        float4 c0 = *(const float4*)&cis[kd * N + d0];
        float4 c1 = *(const float4*)&cis[kd * N + d0 + 4];
        acc[0].x += c0.x*v.x; acc[0].y += c0.x*v.y; acc[0].z += c0.x*v.z; acc[0].w += c0.x*v.w;
        acc[1].x += c0.y*v.x; acc[1].y += c0.y*v.y; acc[1].z += c0.y*v.z; acc[1].w += c0.y*v.w;
        acc[2].x += c0.z*v.x; acc[2].y += c0.z*v.y; acc[2].z += c0.z*v.z; acc[2].w += c0.z*v.w;
        acc[3].x += c0.w*v.x; acc[3].y += c0.w*v.y; acc[3].z += c0.w*v.z; acc[3].w += c0.w*v.w;
        acc[4].x += c1.x*v.x; acc[4].y += c1.x*v.y; acc[4].z += c1.x*v.z; acc[4].w += c1.x*v.w;
        acc[5].x += c1.y*v.x; acc[5].y += c1.y*v.y; acc[5].z += c1.y*v.z; acc[5].w += c1.y*v.w;
        acc[6].x += c1.z*v.x; acc[6].y += c1.z*v.y; acc[6].z += c1.z*v.z; acc[6].w += c1.z*v.w;
        acc[7].x += c1.w*v.x; acc[7].y += c1.w*v.y; acc[7].z += c1.w*v.z; acc[7].w += c1.w*v.w;
    }
    if (act) {
        float* q = g_Y2 + (size_t)bo * (N * MM) + m0;
#pragma unroll
        for (int i = 0; i < 8; i++) *(float4*)(q + (size_t)(d0 + i) * MM) = acc[i];
    }
}

// ---------------------------------------------------------------------------
// inv_hw: U1[slice][kh][kw] -> out[slice][h][w], 1 slice per 128-thread block.
// Output-side butterfly.  tmp row stride 24 -> stage 2 loads via LDS.128.
// ---------------------------------------------------------------------------
template<int HB>
__device__ __forceinline__ void inv_s1(const float* __restrict__ zcol, float* __restrict__ tcol, bool act) {
    float E[8], Od[8];
#pragma unroll
    for (int i = 0; i < 8; i++) { E[i] = 0.f; Od[i] = 0.f; }
    static_for<20>([&](auto KH) {
        constexpr int kh = KH.value;
        float zv = zcol[kh * 20];
        static_for<8>([&](auto I) {
            constexpr int i = I.value;
            constexpr float c = CI(HB + i, kh);
            if constexpr (kh & 1) Od[i] += zv * c; else E[i] += zv * c;
        });
    });
    if (act) {
#pragma unroll
        for (int i = 0; i < 8; i++) {
            tcol[(HB + i) * 24] = E[i] + Od[i];
            tcol[(63 - HB - i) * 24] = E[i] - Od[i];
        }
    }
}

template<int W0>
__device__ __forceinline__ void inv_s2(const float* __restrict__ trow, float* __restrict__ orow) {
    float E[16], Od[16];
#pragma unroll
    for (int i = 0; i < 16; i++) { E[i] = 0.f; Od[i] = 0.f; }
    static_for<5>([&](auto K4) {
        constexpr int k4 = K4.value;
        float4 tv = *(const float4*)(trow + k4 * 4);
        float tvv[4] = {tv.x, tv.y, tv.z, tv.w};
        static_for<4>([&](auto J) {
            constexpr int j = J.value;
            constexpr int kw = k4 * 4 + j;
            float tvj = tvv[j];
            static_for<16>([&](auto I) {
                constexpr int i = I.value;
                constexpr float c = CI(W0 + i, kw);
                if constexpr (kw & 1) Od[i] += tvj * c; else E[i] += tvj * c;
            });
        });
    });
#pragma unroll
    for (int j = 0; j < 4; j++) {
        float4 v = make_float4(E[j*4+0] + Od[j*4+0], E[j*4+1] + Od[j*4+1],
                               E[j*4+2] + Od[j*4+2], E[j*4+3] + Od[j*4+3]);
        *(float4*)(orow + W0 + j * 4) = v;
    }
#pragma unroll
    for (int j = 0; j < 4; j++) {
        float4 v = make_float4(E[15-(j*4+0)] - Od[15-(j*4+0)], E[15-(j*4+1)] - Od[15-(j*4+1)],
                               E[15-(j*4+2)] - Od[15-(j*4+2)], E[15-(j*4+3)] - Od[15-(j*4+3)]);
        *(float4*)(orow + (48 - W0) + j * 4) = v;
    }
}

__global__ __launch_bounds__(128) void inv_hw_k(float* __restrict__ out) {
    __shared__ float zs[MM];
    __shared__ float tmp[64 * 24];
    int t = threadIdx.x, wid = t >> 5, lane = t & 31;
    int slice = blockIdx.x;
    const float* p = g_Y2 + (size_t)slice * MM;
    for (int i = t; i < MM; i += 128) zs[i] = p[i];
    __syncthreads();
    {   // stage 1 (butterfly): tmp[h][kw] from zs[kh][kw]
        bool act = lane < 20;
        int kwc = act ? lane : 0;
        const float* zcol = &zs[kwc];
        float* tcol = &tmp[kwc];
        switch (wid) {
            case 0: inv_s1<0>(zcol, tcol, act); break;
            case 1: inv_s1<8>(zcol, tcol, act); break;
            case 2: inv_s1<16>(zcol, tcol, act); break;
            default: inv_s1<24>(zcol, tcol, act); break;
        }
    }
    __syncthreads();
    {   // stage 2 (butterfly): out[h][w] from tmp[h][kw], direct gmem stores
        int h = (wid & 1) * 32 + lane;
        const float* trow = &tmp[h * 24];
        float* orow = out + (size_t)slice * NN + h * 64;
        if (wid >> 1) inv_s2<16>(trow, orow); else inv_s2<0>(trow, orow);
    }
}

// ---------------------------------------------------------------------------
extern "C" void kernel_launch(void* const* d_in, const int* in_sizes, int n_in,
                              void* d_out, int out_size) {
    const float* x = (const float*)d_in[0];       // (2,32,64,64,64)
    const float* w = (const float*)d_in[1];       // (32,32,20,20,20)
    float* out = (float*)d_out;                   // (2,32,64,64,64)

    fwd_wh_k<<<B * C * N, 128>>>(x);              // 4096 blocks
    {
        dim3 g(B * C, 4);
        fwd_d_k<<<g, 128>>>();                    // 256 blocks
    }
    {
        dim3 g(63, 8, 4);
        mix_k<<<g, 128>>>(w);                     // 2016 blocks
    }
    {
        dim3 g(B * O, 4);
        inv_d_k<<<g, 256>>>();                    // 256 blocks
    }
    inv_hw_k<<<B * O * N, 128>>>(out);            // 4096 blocks
}